// round 13
// baseline (speedup 1.0000x reference)
#include <cuda_runtime.h>
#include <cuda_fp16.h>
#include <math.h>

#define Bsz 128
#define Tt  256
#define Hd  1024
#define BT  (Bsz * Tt)
#define BH  (Bsz * Hd)

// Scratch (device globals). Fragments are fp16 packed as half2-in-u32.
__device__ __align__(16) unsigned g_xfrag[(size_t)BT * Hd / 2]; // x fragments (64 MiB)
__device__ __align__(16) float g_h0f[BH];                   // final h0 (fp32)
__device__ __align__(16) unsigned g_h0frag[4][BH / 2];      // h0 fragments, depth-4 ring
__device__ __align__(16) unsigned g_h1frag[2][BH / 2];      // h1 fragments, parity
__device__ int g_barA, g_barB;                              // group phase barriers (monotonic)

// ---------------------------------------------------------------------------
__device__ __forceinline__ unsigned f2h2(float lo, float hi) {
    __half2 h = __floats2half2_rn(lo, hi);
    return *(unsigned*)&h;
}
__device__ __forceinline__ int ld_acq(const int* a) {
    int v; asm volatile("ld.acquire.gpu.s32 %0, [%1];" : "=r"(v) : "l"(a) : "memory"); return v;
}
__device__ __forceinline__ void red_release(int* a) {
    asm volatile("red.release.gpu.global.add.s32 [%0], 1;" :: "l"(a) : "memory");
}
__device__ __forceinline__ void wait_ge(const int* a, int tgt) {
    if (ld_acq(a) >= tgt) return;
    while (ld_acq(a) < tgt) __nanosleep(32);
}
__device__ __forceinline__ void prefetchL2(const void* p) {
    asm volatile("prefetch.global.L2 [%0];" :: "l"(p));
}

// m16n8k16 fp16 MMA, fp32 accumulate
#define MMA_F16(C, A, B)                                                      \
    asm volatile(                                                             \
        "mma.sync.aligned.m16n8k16.row.col.f32.f16.f16.f32 "                  \
        "{%0,%1,%2,%3}, {%4,%5,%6,%7}, {%8,%9}, {%0,%1,%2,%3};"               \
        : "+f"((C)[0]), "+f"((C)[1]), "+f"((C)[2]), "+f"((C)[3])              \
        : "r"((A).x), "r"((A).y), "r"((A).z), "r"((A).w),                     \
          "r"((B).x), "r"((B).y))

// u32 index of the half2 holding A-elements (b, n),(b, n+1); n even. (validated R12)
__device__ __forceinline__ int fidx2(int b, int n) {
    int kc = n & 15;
    int lane = (b & 7) * 4 + ((kc >> 1) & 3);
    int reg  = ((b >> 3) & 1) + ((kc >> 3) << 1);
    return (((n >> 4) * 8 + (b >> 4)) * 32 + lane) * 4 + reg;
}

// ---------------------------------------------------------------------------
__global__ void init_kernel(const float* __restrict__ h0in)
{
    int idx = blockIdx.x * blockDim.x + threadIdx.x;
    if (idx == 0) { g_barA = 0; g_barB = 0; }
    for (int e = idx; e < 2 * (BH / 2); e += gridDim.x * blockDim.x) {
        int which = e >> 16;               // 0: layer0, 1: layer1
        int r = e & (BH / 2 - 1);
        int b = r >> 9;
        int n = (r & 511) * 2;
        unsigned v = f2h2(h0in[which * Hd + n], h0in[which * Hd + n + 1]);
        if (which == 0) g_h0frag[3][fidx2(b, n)] = v;   // A(0) reads slot (0-1)&3 = 3
        else            g_h1frag[1][fidx2(b, n)] = v;   // B(1) reads slot (1-2)&1 = 1
    }
}

__global__ void xprep_kernel(const float* __restrict__ x)
{
    const int total = BT * Hd / 4;
    for (int e = blockIdx.x * blockDim.x + threadIdx.x; e < total;
         e += gridDim.x * blockDim.x) {
        int n  = (e & 255) * 4;
        int bt = e >> 8;
        int b  = bt >> 8;
        int t  = bt & 255;
        float4 v = *(const float4*)(x + (size_t)e * 4);
        unsigned* dst = g_xfrag + (size_t)t * (BH / 2);
        dst[fidx2(b, n + 0)] = f2h2(v.x, v.y);
        dst[fidx2(b, n + 2)] = f2h2(v.z, v.w);
    }
}

// ---------------------------------------------------------------------------
// One full-K sub-GEMM: c[4][4] += A(frag stream) * W(smem frags).
// Warp covers K-half kg*512, m-tile wm, n-tiles 0..3 of the block's 32 cols.
// ---------------------------------------------------------------------------
__device__ __forceinline__ void gemm_acc(float (&c)[4][4], const uint4* afrag,
                                         const unsigned* Wb, int kg, int wm, int lane)
{
    const uint4* ab = afrag + ((size_t)(kg * 32) * 8 + wm) * 32 + lane;
    uint4 pa[8];
#pragma unroll
    for (int i = 0; i < 8; i++) pa[i] = __ldcg(ab + i * 256);
#pragma unroll
    for (int k16l = 0; k16l < 32; k16l++) {
        uint4 a = pa[k16l & 7];
        if (k16l < 24) pa[k16l & 7] = __ldcg(ab + (k16l + 8) * 256);
        const int k16 = kg * 32 + k16l;
#pragma unroll
        for (int nt = 0; nt < 4; nt++) {
            uint2 b = *(const uint2*)&Wb[((k16 * 4 + nt) * 32 + lane) * 2];
            MMA_F16(c[nt], a, b);
        }
    }
}

// Preload one [1024 x 32] weight tile (cols n0..n0+31) into fp16 fragment smem.
__device__ __forceinline__ void preload_w(unsigned* Wb, const float* __restrict__ Wsrc,
                                          int n0, int tid)
{
#pragma unroll
    for (int i = 0; i < 8; i++) {
        int idx = tid + 512 * i;              // 4096 = 512 k-pairs x 8 col-groups
        int kp  = idx >> 3;
        int c4  = idx & 7;
        int k0  = 2 * kp;
        float4 w0 = *(const float4*)(Wsrc + (size_t)k0 * Hd + n0 + c4 * 4);
        float4 w1 = *(const float4*)(Wsrc + (size_t)(k0 + 1) * Hd + n0 + c4 * 4);
        int k16 = k0 >> 4, kk = k0 & 15;
        float a0[4] = {w0.x, w0.y, w0.z, w0.w};
        float a1[4] = {w1.x, w1.y, w1.z, w1.w};
#pragma unroll
        for (int j = 0; j < 4; j++) {
            int nl = c4 * 4 + j;
            int nt = nl >> 3, n_in = nl & 7;
            Wb[((k16 * 4 + nt) * 32 + n_in * 4 + ((kk & 7) >> 1)) * 2 + (kk >> 3)] =
                f2h2(a0[j], a1[j]);
        }
    }
}

// ---------------------------------------------------------------------------
// Persistent kernel. 64 blocks x 512 threads, fully fused per-tile updates.
//   bid 0..31  (A): h0_p = tanh(x_p@Wi0 + h0_{p-1}@Wh0 + bi0+bh0), 32-col tile.
//       x-GEMM first (no dependency), THEN wait barA>=32p (+WAR barB>=32(p-3)),
//       then h-GEMM, fold, register epilogue -> h0frag[p&3]; arrive barA.
//   bid 32..63 (B): h1_{p-1} = tanh(h0_{p-1}@Wi1 + h1_{p-2}@Wh1 + bi1+bh1).
//       wait barB>=32(p-1), h1-GEMM; wait barA>=32p, h0-GEMM; epilogue ->
//       out[:,p-1,:] + h1frag[(p-1)&1]; arrive barB.
// No partial buffers, no combine counters. smem = 2x64KB weights + 16KB red.
// ---------------------------------------------------------------------------
extern __shared__ unsigned smemAll[];   // W1:16384 | W2:16384 | red 16KB

__global__ __launch_bounds__(512, 1) void persistent_kernel(
    const float* __restrict__ Wi, const float* __restrict__ bi,
    const float* __restrict__ Wh, const float* __restrict__ bh,
    float* __restrict__ out)
{
    const int bid  = blockIdx.x;
    const bool isA = (bid < 32);
    const int tile = isA ? bid : bid - 32;
    const int n0   = tile * 32;

    const int tid  = threadIdx.x;
    const int lane = tid & 31;
    const int wid  = tid >> 5;
    const int wm   = wid & 7;             // M-tile (16 rows)
    const int kg   = wid >> 3;            // K-half (512)

    unsigned* W1 = smemAll;               // A: Wi0 ; B: Wh1
    unsigned* W2 = smemAll + 16384;       // A: Wh0 ; B: Wi1
    float4*  red = (float4*)(smemAll + 32768);   // [8 wm][4 nt][32 lane]

    preload_w(W1, isA ? Wi : Wh + (size_t)Hd * Hd, n0, tid);
    preload_w(W2, isA ? Wh : Wi + (size_t)Hd * Hd, n0, tid);
    __syncthreads();

    const int pstart = isA ? 0 : 1;
    const int pend   = isA ? Tt - 1 : Tt;

    for (int p = pstart; p <= pend; ++p) {
        float c[4][4];
#pragma unroll
        for (int nt = 0; nt < 4; nt++)
#pragma unroll
            for (int r = 0; r < 4; r++) c[nt][r] = 0.0f;

        if (isA) {
            // dependency-free x-GEMM first (runs in the slack)
            gemm_acc(c, (const uint4*)(g_xfrag + (size_t)p * (BH / 2)), W1, kg, wm, lane);
            // prefetch next phase's x slice portion (64 of 2048 lines per block)
            if (p + 1 < Tt && tid < 64)
                prefetchL2((const char*)(g_xfrag + (size_t)(p + 1) * (BH / 2))
                           + ((size_t)tile * 64 + tid) * 128);
            if (tid == 0 && p > 0) wait_ge(&g_barA, 32 * p);
            if (tid == 1 && p >= 4) wait_ge(&g_barB, 32 * (p - 3));  // WAR h0frag[p&3]
            __syncthreads();
            gemm_acc(c, (const uint4*)g_h0frag[(p - 1) & 3], W2, kg, wm, lane);
        } else {
            if (tid == 0 && p >= 2) wait_ge(&g_barB, 32 * (p - 1));  // h1_{p-2} ready
            __syncthreads();
            gemm_acc(c, (const uint4*)g_h1frag[(p - 2) & 1], W1, kg, wm, lane);
            if (tid == 0) wait_ge(&g_barA, 32 * p);                  // h0_{p-1} ready
            __syncthreads();
            gemm_acc(c, (const uint4*)g_h0frag[(p - 1) & 3], W2, kg, wm, lane);
        }

        // ---- kg fold: kg1 -> smem, kg0 adds ----
        if (kg == 1) {
#pragma unroll
            for (int nt = 0; nt < 4; nt++)
                red[(wm * 4 + nt) * 32 + lane] =
                    make_float4(c[nt][0], c[nt][1], c[nt][2], c[nt][3]);
        }
        __syncthreads();

        // ---- register-resident epilogue (kg0 warps) ----
        if (kg == 0) {
            const int gq = lane >> 2, tq = lane & 3;
            const int r0 = wm * 16 + gq, r1 = r0 + 8;
            if (isA) {
                unsigned* dstf = g_h0frag[p & 3];
#pragma unroll
                for (int nt = 0; nt < 4; nt++) {
                    float4 rr = red[(wm * 4 + nt) * 32 + lane];
                    const int ng = n0 + nt * 8 + 2 * tq;
                    float2 bb1 = *(const float2*)&bi[ng];
                    float2 bb2 = *(const float2*)&bh[ng];
                    float bs0 = bb1.x + bb2.x, bs1 = bb1.y + bb2.y;
                    float v00 = tanhf(c[nt][0] + rr.x + bs0);
                    float v01 = tanhf(c[nt][1] + rr.y + bs1);
                    float v10 = tanhf(c[nt][2] + rr.z + bs0);
                    float v11 = tanhf(c[nt][3] + rr.w + bs1);
                    if (p == Tt - 1) {
                        *(float2*)&g_h0f[(size_t)r0 * Hd + ng] = make_float2(v00, v01);
                        *(float2*)&g_h0f[(size_t)r1 * Hd + ng] = make_float2(v10, v11);
                    }
                    dstf[fidx2(r0, ng)] = f2h2(v00, v01);
                    dstf[fidx2(r1, ng)] = f2h2(v10, v11);
                }
            } else {
                const int tt = p - 1;
                unsigned* dstf = g_h1frag[(p - 1) & 1];
#pragma unroll
                for (int nt = 0; nt < 4; nt++) {
                    float4 rr = red[(wm * 4 + nt) * 32 + lane];
                    const int ng = n0 + nt * 8 + 2 * tq;
                    float2 bb1 = *(const float2*)&bi[Hd + ng];
                    float2 bb2 = *(const float2*)&bh[Hd + ng];
                    float bs0 = bb1.x + bb2.x, bs1 = bb1.y + bb2.y;
                    float v00 = tanhf(c[nt][0] + rr.x + bs0);
                    float v01 = tanhf(c[nt][1] + rr.y + bs1);
                    float v10 = tanhf(c[nt][2] + rr.z + bs0);
                    float v11 = tanhf(c[nt][3] + rr.w + bs1);
                    *(float2*)&out[((size_t)r0 * Tt + tt) * Hd + ng] = make_float2(v00, v01);
                    *(float2*)&out[((size_t)r1 * Tt + tt) * Hd + ng] = make_float2(v10, v11);
                    dstf[fidx2(r0, ng)] = f2h2(v00, v01);
                    dstf[fidx2(r1, ng)] = f2h2(v10, v11);
                }
            }
        }

        // ---- phase arrival (release publishes this block's writes) ----
        __syncthreads();
        if (tid == 0) red_release(isA ? &g_barA : &g_barB);
    }
}

// ---------------------------------------------------------------------------
// Finalize: h_n[b][0] = h0_{T-1}, h_n[b][1] = h1_{T-1} (= out[:,T-1,:])
// ---------------------------------------------------------------------------
__global__ void finalize_kernel(float* __restrict__ out)
{
    int idx = blockIdx.x * blockDim.x + threadIdx.x;
    if (idx >= BH) return;
    int b = idx / Hd, h = idx % Hd;
    float* hn = out + (size_t)BT * Hd;
    hn[((size_t)b * 2 + 0) * Hd + h] = g_h0f[(size_t)b * Hd + h];
    hn[((size_t)b * 2 + 1) * Hd + h] = out[((size_t)b * Tt + (Tt - 1)) * Hd + h];
}

// ---------------------------------------------------------------------------
extern "C" void kernel_launch(void* const* d_in, const int* in_sizes, int n_in,
                              void* d_out, int out_size)
{
    const float* x    = (const float*)d_in[0];   // [B,T,H]
    const float* h0in = (const float*)d_in[1];   // [1,L,H]
    const float* Wi   = (const float*)d_in[2];   // [L,H,H]
    const float* bi   = (const float*)d_in[3];   // [L,H]
    const float* Wh   = (const float*)d_in[4];   // [L,H,H]
    const float* bh   = (const float*)d_in[5];   // [L,H]
    float* out = (float*)d_out;                  // [B,T,H] then [B,L,H]

    init_kernel<<<256, 256>>>(h0in);
    xprep_kernel<<<8192, 256>>>(x);

    cudaFuncSetAttribute(persistent_kernel,
                         cudaFuncAttributeMaxDynamicSharedMemorySize, 147456);
    persistent_kernel<<<64, 512, 147456>>>(Wi, bi, Wh, bh, out);

    finalize_kernel<<<(BH + 255) / 256, 256>>>(out);
}